// round 12
// baseline (speedup 1.0000x reference)
#include <cuda_runtime.h>
#include <cstdint>

// MeanAggregator: out[b, :] = (1/K) * sum_k embed[neigh_ids[b,k], :]
// B=8192, K=32, D=128, embed: [V=100000, 128] fp32.
//
// Warp-per-row, lane k holds neighbor id k, __shfl broadcast, coalesced
// LDG.128 gathers, unroll(8) for MLP. At ~90% of the LTS cap; this round
// shrinks the CTA work quantum (64-thread blocks -> 4096 CTAs of 2 rows) so
// CLC work-stealing rebalances the single-wave tail across slow/fast SMs.
//
// Index width (JAX delivers int32 despite the int64 reference signature when
// x64 is off) detected via a SAFE uniform probe of the first 256 bytes.

static constexpr int B = 8192;
static constexpr int K = 32;
static constexpr int D4 = 32;           // D/4
static constexpr long long V = 100000;
static constexpr int NIDS = B * K;

__global__ __launch_bounds__(64) void mean_agg_kernel(
    const void* __restrict__ neigh_ids_raw,    // [B, K] int32 or int64
    const float4* __restrict__ embed,          // [V, D4]
    float4* __restrict__ out)                  // [B, D4]
{
    const int warp_global = (blockIdx.x * blockDim.x + threadIdx.x) >> 5;
    const int lane = threadIdx.x & 31;

    // Uniform width probe on the first 256 bytes (in-bounds either way).
    // int32 data: odd 4-byte words are random ids -> some probe fails [0,V).
    long long probe = ((const long long*)neigh_ids_raw)[lane];
    bool in_range = (probe >= 0) && (probe < V);
    bool ids_are_64 = __all_sync(0xffffffffu, in_range);

    // Lane k holds the k-th neighbor id for this row, at the detected width.
    int my_id;
    if (ids_are_64) {
        my_id = (int)((const long long*)neigh_ids_raw)[warp_global * K + lane];
    } else {
        my_id = ((const int*)neigh_ids_raw)[warp_global * K + lane];
    }

    float4 acc = make_float4(0.f, 0.f, 0.f, 0.f);

#pragma unroll 8
    for (int k = 0; k < K; ++k) {
        unsigned nid = (unsigned)__shfl_sync(0xffffffffu, my_id, k);
        float4 v = __ldg(&embed[nid * D4 + lane]);
        acc.x += v.x;
        acc.y += v.y;
        acc.z += v.z;
        acc.w += v.w;
    }

    const float inv_k = 1.0f / (float)K;
    acc.x *= inv_k;
    acc.y *= inv_k;
    acc.z *= inv_k;
    acc.w *= inv_k;

    // Streaming store: output has no reuse inside the kernel.
    __stcg(&out[warp_global * D4 + lane], acc);
}

extern "C" void kernel_launch(void* const* d_in, const int* in_sizes, int n_in,
                              void* d_out, int out_size)
{
    // Identify inputs by element count, not position.
    const void* neigh_ids = d_in[0];
    const void* embed = d_in[1];
    if (n_in >= 2) {
        if (in_sizes[0] == (int)(V * 128) || in_sizes[1] == NIDS) {
            embed = d_in[0];
            neigh_ids = d_in[1];
        }
    }

    // 64-thread blocks: 4096 CTAs of 2 rows -> fine tail quantum; CLC
    // work-stealing distributes the tail across SMs.
    const int threads = 64;                  // 2 warps/block
    const int blocks = B / (threads / 32);   // 4096
    mean_agg_kernel<<<blocks, threads>>>(neigh_ids, (const float4*)embed,
                                         (float4*)d_out);
}

// round 13
// speedup vs baseline: 1.3342x; 1.3342x over previous
#include <cuda_runtime.h>
#include <cstdint>

// MeanAggregator: out[b, :] = (1/K) * sum_k embed[neigh_ids[b,k], :]
// B=8192, K=32, D=128, embed: [V=100000, 128] fp32.
//
// FINAL CONFIG (established best, 12.77us over two independent benches):
// single kernel, warp-per-row, 128-thread blocks (2048 CTAs, one wave),
// lane k holds neighbor id k, __shfl broadcast, coalesced LDG.128 gathers,
// unroll(8) for MLP, __stcg streaming store.
//
// Measured regime: warm L2-resident (51 MB table), ~10.9 TB/s through LTS
// (~90% of the path-independent cap). Compute pipes idle; traffic
// irreducible (row reuse 2.6x, fp16 conversion pass costs more than it
// saves). Rejected by measurement: extra prelude launches (+2us), 64-thr
// blocks (+4.2us), 256-thr blocks (+1.7us), unroll(32) (neutral).
//
// Index width (JAX delivers int32 despite the int64 reference signature when
// x64 is off) detected via a SAFE uniform probe of the first 256 bytes:
// int32 data has random ids in the odd 4-byte words -> the [0,V) vote on
// int64-interpreted values fails with certainty; genuine int64 always passes.

static constexpr int B = 8192;
static constexpr int K = 32;
static constexpr int D4 = 32;           // D/4
static constexpr long long V = 100000;
static constexpr int NIDS = B * K;

__global__ __launch_bounds__(128) void mean_agg_kernel(
    const void* __restrict__ neigh_ids_raw,    // [B, K] int32 or int64
    const float4* __restrict__ embed,          // [V, D4]
    float4* __restrict__ out)                  // [B, D4]
{
    const int warp_global = (blockIdx.x * blockDim.x + threadIdx.x) >> 5;
    const int lane = threadIdx.x & 31;

    // Uniform width probe on the first 256 bytes (in-bounds either way).
    long long probe = ((const long long*)neigh_ids_raw)[lane];
    bool in_range = (probe >= 0) && (probe < V);
    bool ids_are_64 = __all_sync(0xffffffffu, in_range);

    // Lane k holds the k-th neighbor id for this row, at the detected width.
    int my_id;
    if (ids_are_64) {
        my_id = (int)((const long long*)neigh_ids_raw)[warp_global * K + lane];
    } else {
        my_id = ((const int*)neigh_ids_raw)[warp_global * K + lane];
    }

    float4 acc = make_float4(0.f, 0.f, 0.f, 0.f);

#pragma unroll 8
    for (int k = 0; k < K; ++k) {
        unsigned nid = (unsigned)__shfl_sync(0xffffffffu, my_id, k);
        float4 v = __ldg(&embed[nid * D4 + lane]);
        acc.x += v.x;
        acc.y += v.y;
        acc.z += v.z;
        acc.w += v.w;
    }

    const float inv_k = 1.0f / (float)K;
    acc.x *= inv_k;
    acc.y *= inv_k;
    acc.z *= inv_k;
    acc.w *= inv_k;

    // Streaming store: output has no reuse inside the kernel.
    __stcg(&out[warp_global * D4 + lane], acc);
}

extern "C" void kernel_launch(void* const* d_in, const int* in_sizes, int n_in,
                              void* d_out, int out_size)
{
    // Identify inputs by element count, not position.
    const void* neigh_ids = d_in[0];
    const void* embed = d_in[1];
    if (n_in >= 2) {
        if (in_sizes[0] == (int)(V * 128) || in_sizes[1] == NIDS) {
            embed = d_in[0];
            neigh_ids = d_in[1];
        }
    }

    // 128-thread blocks: 2048 CTAs, single wave across 148 SMs.
    const int threads = 128;                 // 4 warps/block
    const int blocks = B / (threads / 32);   // 2048
    mean_agg_kernel<<<blocks, threads>>>(neigh_ids, (const float4*)embed,
                                         (float4*)d_out);
}